// round 15
// baseline (speedup 1.0000x reference)
#include <cuda_runtime.h>
#include <cuda_fp16.h>
#include <cstdint>

// ---------------- problem constants ----------------
#define B_     4
#define C_     512
#define TH_    16384
#define MTOT_  (B_ * TH_)
#define KW_    768
#define AUX_   256
#define OUT_   512

// ---------------- tiling ----------------
#define BM 64
#define BK 32
#define NS (C_ / BK)            // 16 stages
#define NTHR 512
// stage layout (bytes): A 4K | W 40960
#define ST_A    0
#define ST_W    4096
#define ST_SZ   45056
#define WROWB 80

// epilogue smem (floats, overlaid on stage memory)
#define EZS 520
#define ZB_F   (BM * EZS)               // 33280
#define PART_F (ZB_F)                   // part[8][64][2]
#define MU_F   (PART_F + 1024)
#define RS_F   (MU_F + 64)
#define SMEM_TOTAL 137728

// ---------------- device scratch ----------------
__device__ __align__(16) __half g_Wh[(size_t)OUT_ * C_];
__device__ float g_sproj[B_ * OUT_];

// ---------------- asm helpers ----------------
__device__ __forceinline__ uint32_t smem_u32(const void* p) {
    uint32_t a;
    asm("{ .reg .u64 t; cvta.to.shared.u64 t, %1; cvt.u32.u64 %0, t; }" : "=r"(a) : "l"(p));
    return a;
}
__device__ __forceinline__ void cp_async16(uint32_t dst, const void* src) {
    asm volatile("cp.async.cg.shared.global [%0], [%1], 16;" :: "r"(dst), "l"(src) : "memory");
}
#define CP_COMMIT() asm volatile("cp.async.commit_group;" ::: "memory")
#define CP_WAIT(n)  asm volatile("cp.async.wait_group %0;" :: "n"(n) : "memory")

__device__ __forceinline__ void ldm_x4(uint32_t* r, uint32_t addr) {
    asm volatile("ldmatrix.sync.aligned.m8n8.x4.shared.b16 {%0,%1,%2,%3}, [%4];"
                 : "=r"(r[0]), "=r"(r[1]), "=r"(r[2]), "=r"(r[3]) : "r"(addr));
}
__device__ __forceinline__ void ldm_x4_t(uint32_t* r, uint32_t addr) {
    asm volatile("ldmatrix.sync.aligned.m8n8.x4.trans.shared.b16 {%0,%1,%2,%3}, [%4];"
                 : "=r"(r[0]), "=r"(r[1]), "=r"(r[2]), "=r"(r[3]) : "r"(addr));
}
__device__ __forceinline__ void mma16816(float* d, const uint32_t* a, const uint32_t* b) {
    asm volatile(
        "mma.sync.aligned.m16n8k16.row.col.f32.f16.f16.f32 "
        "{%0,%1,%2,%3},{%4,%5,%6,%7},{%8,%9},{%0,%1,%2,%3};"
        : "+f"(d[0]), "+f"(d[1]), "+f"(d[2]), "+f"(d[3])
        : "r"(a[0]), "r"(a[1]), "r"(a[2]), "r"(a[3]), "r"(b[0]), "r"(b[1]));
}
__device__ __forceinline__ void sts64(uint32_t dst, uint32_t a, uint32_t b) {
    asm volatile("st.shared.v2.b32 [%0], {%1,%2};" :: "r"(dst), "r"(a), "r"(b) : "memory");
}

// convert 4 floats -> fp16 pair-packed (2 u32)
__device__ __forceinline__ void cvt4h(const float* f, uint32_t* hi) {
    unsigned short h[4];
#pragma unroll
    for (int j = 0; j < 4; ++j) h[j] = __half_as_ushort(__float2half_rn(f[j]));
    hi[0] = (uint32_t)h[0] | ((uint32_t)h[1] << 16);
    hi[1] = (uint32_t)h[2] | ((uint32_t)h[3] << 16);
}

// ---------------- prep kernels ----------------
__global__ void sproj_kernel(const float* __restrict__ s, const float* __restrict__ W,
                             const float* __restrict__ bias) {
    __shared__ float ss[AUX_];
    const int b = blockIdx.x, o0 = blockIdx.y * 64;
    const int tid = threadIdx.x, lane = tid & 31, warp = tid >> 5;
    if (tid < AUX_) ss[tid] = s[b * AUX_ + tid];
    __syncthreads();
    float sl[8];
    *(float4*)&sl[0] = *(const float4*)&ss[lane * 8];
    *(float4*)&sl[4] = *(const float4*)&ss[lane * 8 + 4];
#pragma unroll
    for (int i = 0; i < 8; ++i) {
        const int o = o0 + warp * 8 + i;
        const float* wr = W + (size_t)o * KW_ + C_ + lane * 8;
        float4 w0 = *(const float4*)wr;
        float4 w1 = *(const float4*)(wr + 4);
        float acc = sl[0] * w0.x + sl[1] * w0.y + sl[2] * w0.z + sl[3] * w0.w +
                    sl[4] * w1.x + sl[5] * w1.y + sl[6] * w1.z + sl[7] * w1.w;
#pragma unroll
        for (int off = 16; off; off >>= 1) acc += __shfl_xor_sync(0xffffffffu, acc, off);
        if (lane == 0) g_sproj[b * OUT_ + o] = acc + bias[o];
    }
}

__global__ void wprep_kernel(const float* __restrict__ W) {
    int n = blockIdx.x, t = threadIdx.x;
#pragma unroll
    for (int r = 0; r < 2; ++r) {
        int k = t + r * 256;
        g_Wh[(size_t)n * C_ + k] = __float2half_rn(W[(size_t)n * KW_ + k]);
    }
}

// ---------------- fused GEMM + PReLU + LN + residual ----------------
__global__ __launch_bounds__(NTHR, 1)
void fused_kernel(const float* __restrict__ x, const float* __restrict__ prelu2_a,
                  const float* __restrict__ lnw, const float* __restrict__ lnb,
                  float* __restrict__ out) {
    extern __shared__ char smem[];
    const uint32_t sb = smem_u32(smem);
    float* smf = (float*)smem;

    const int tid = threadIdx.x, lane = tid & 31, wid = tid >> 5;
    const int wm = wid & 1, wn = wid >> 1;        // 2 x 8 warp grid
    const int mwarp = wm * 32, nwarp = wn * 64;
    const int m0 = blockIdx.x * BM;
    const int bi = m0 >> 14, mb = m0 & (TH_ - 1);
    const float* xb = x + (size_t)bi * C_ * TH_ + mb;

    const int ka = tid >> 4, mo4 = tid & 15;
    const uint32_t a_sts_off = ka * 128 + (((mo4 >> 1) ^ (ka & 7)) << 4) + (mo4 & 1) * 8;
    const float* a_src = xb + (size_t)ka * TH_ + mo4 * 4;

    const int krl = (lane & 7) + ((lane >> 4) & 1) * 8;
    const int mcl = ((lane >> 3) & 1) * 8;
    uint32_t cA[2];
#pragma unroll
    for (int i = 0; i < 2; ++i)
        cA[i] = krl * 128 + ((((mwarp + i * 16 + mcl) >> 3) ^ (krl & 7)) << 4);
    const int nll = (lane & 7) + ((lane >> 4) & 1) * 8;
    const int kcl = ((lane >> 3) & 1) * 8;
    const uint32_t cB = (nwarp + nll) * WROWB + kcl * 2;

    float acc[2][8][4];
#pragma unroll
    for (int i = 0; i < 2; ++i)
#pragma unroll
        for (int j = 0; j < 8; ++j)
#pragma unroll
            for (int q = 0; q < 4; ++q) acc[i][j][q] = 0.f;

    auto issue_W = [&](int s) {
        const uint32_t wb = sb + (s & 1) * ST_SZ + ST_W;
        const int kk = s * BK;
#pragma unroll
        for (int r = 0; r < 4; ++r) {
            const int n = r * 128 + (tid >> 2);
            const int kc = tid & 3;
            cp_async16(wb + n * WROWB + kc * 16, g_Wh + (size_t)n * C_ + kk + kc * 8);
        }
        CP_COMMIT();
    };
    auto ldg_A = [&](int s, float4& f) {
        f = *(const float4*)(a_src + (size_t)s * BK * TH_);
    };
    auto sts_A = [&](int s, const float4& f) {
        const uint32_t ab = sb + (s & 1) * ST_SZ;
        uint32_t hi[2];
        cvt4h((const float*)&f, hi);
        sts64(ab + ST_A + a_sts_off, hi[0], hi[1]);
    };

    // ---- prologue ----
    {
        float4 f0;
        ldg_A(0, f0);
        issue_W(0);
        sts_A(0, f0);
        CP_WAIT(0);
        __syncthreads();
    }

    // ---- mainloop ----
    for (int s = 0; s < NS; ++s) {
        const bool pf = (s + 1 < NS);
        float4 fr;
        if (pf) { issue_W(s + 1); ldg_A(s + 1, fr); }

        const uint32_t stb = sb + (s & 1) * ST_SZ;
#pragma unroll
        for (int h16 = 0; h16 < 2; ++h16) {
            uint32_t aH[2][4];
#pragma unroll
            for (int i = 0; i < 2; ++i)
                ldm_x4_t(aH[i], stb + ST_A + h16 * 2048 + cA[i]);
#pragma unroll
            for (int j2 = 0; j2 < 4; ++j2) {
                uint32_t bH[4];
                ldm_x4(bH, stb + ST_W + cB + j2 * (16 * WROWB) + h16 * 32);
#pragma unroll
                for (int i = 0; i < 2; ++i)
#pragma unroll
                    for (int jj = 0; jj < 2; ++jj)
                        mma16816(acc[i][j2 * 2 + jj], aH[i], &bH[jj * 2]);
            }
        }
        if (pf) {
            sts_A(s + 1, fr);
            CP_WAIT(0);
        }
        __syncthreads();
    }

    // ---- in-kernel epilogue ----
    const float a2 = *prelu2_a;
    float2 spv[8];
#pragma unroll
    for (int j = 0; j < 8; ++j)
        spv[j] = *(const float2*)&g_sproj[bi * OUT_ + nwarp + j * 8 + (lane & 3) * 2];

    float su[4] = {0.f, 0.f, 0.f, 0.f}, sq[4] = {0.f, 0.f, 0.f, 0.f};
#pragma unroll
    for (int i = 0; i < 2; ++i)
#pragma unroll
        for (int j = 0; j < 8; ++j)
#pragma unroll
            for (int q = 0; q < 4; ++q) {
                float v = acc[i][j][q] + ((q & 1) ? spv[j].y : spv[j].x);
                v = (v >= 0.f) ? v : a2 * v;
                acc[i][j][q] = v;
                const int si = i * 2 + (q >> 1);
                su[si] += v; sq[si] += v * v;
            }
#pragma unroll
    for (int si = 0; si < 4; ++si) {
#pragma unroll
        for (int off = 1; off <= 2; off <<= 1) {
            su[si] += __shfl_xor_sync(0xffffffffu, su[si], off);
            sq[si] += __shfl_xor_sync(0xffffffffu, sq[si], off);
        }
    }
    if ((lane & 3) == 0) {
#pragma unroll
        for (int si = 0; si < 4; ++si) {
            const int tok = mwarp + (si >> 1) * 16 + (si & 1) * 8 + (lane >> 2);
            smf[PART_F + wn * 128 + tok * 2] = su[si];
            smf[PART_F + wn * 128 + tok * 2 + 1] = sq[si];
        }
    }
#pragma unroll
    for (int i = 0; i < 2; ++i) {
        const int tok = mwarp + i * 16 + (lane >> 2);
#pragma unroll
        for (int j = 0; j < 8; ++j) {
            const int c = nwarp + j * 8 + (lane & 3) * 2;
            *(float2*)&smf[tok * EZS + c] = make_float2(acc[i][j][0], acc[i][j][1]);
            *(float2*)&smf[(tok + 8) * EZS + c] = make_float2(acc[i][j][2], acc[i][j][3]);
        }
    }
    __syncthreads();

    if (tid < 64) {
        float s0 = 0.f, s1 = 0.f;
#pragma unroll
        for (int w = 0; w < 8; ++w) {
            s0 += smf[PART_F + w * 128 + tid * 2];
            s1 += smf[PART_F + w * 128 + tid * 2 + 1];
        }
        const float mu = s0 * (1.f / 512.f);
        smf[MU_F + tid] = mu;
        smf[RS_F + tid] = rsqrtf(s1 * (1.f / 512.f) - mu * mu + 1e-8f);
    }
    __syncthreads();

    {
        const int o = tid;
        const float lw = lnw[o], lb = lnb[o];
        const size_t gbase = ((size_t)(bi * OUT_ + o)) * TH_ + mb;
#pragma unroll 4
        for (int mq = 0; mq < BM; mq += 4) {
            float4 xv = *(const float4*)(x + gbase + mq);
            float4 yv;
            yv.x = xv.x + (smf[(mq + 0) * EZS + o] - smf[MU_F + mq + 0]) * smf[RS_F + mq + 0] * lw + lb;
            yv.y = xv.y + (smf[(mq + 1) * EZS + o] - smf[MU_F + mq + 1]) * smf[RS_F + mq + 1] * lw + lb;
            yv.z = xv.z + (smf[(mq + 2) * EZS + o] - smf[MU_F + mq + 2]) * smf[RS_F + mq + 2] * lw + lb;
            yv.w = xv.w + (smf[(mq + 3) * EZS + o] - smf[MU_F + mq + 3]) * smf[RS_F + mq + 3] * lw + lb;
            *(float4*)(out + gbase + mq) = yv;
        }
    }
}

// ---------------- launch ----------------
extern "C" void kernel_launch(void* const* d_in, const int* in_sizes, int n_in,
                              void* d_out, int out_size) {
    (void)in_sizes; (void)n_in; (void)out_size;
    const float* x        = (const float*)d_in[0];
    const float* s        = (const float*)d_in[1];
    const float* W        = (const float*)d_in[5];
    const float* bias     = (const float*)d_in[6];
    const float* prelu2_a = (const float*)d_in[7];
    const float* ln2_w    = (const float*)d_in[8];
    const float* ln2_b    = (const float*)d_in[9];
    float* out = (float*)d_out;

    cudaFuncSetAttribute(fused_kernel, cudaFuncAttributeMaxDynamicSharedMemorySize, SMEM_TOTAL);

    sproj_kernel<<<dim3(B_, OUT_ / 64), 256>>>(s, W, bias);
    wprep_kernel<<<OUT_, 256>>>(W);
    fused_kernel<<<MTOT_ / BM, NTHR, SMEM_TOTAL>>>(x, prelu2_a, ln2_w, ln2_b, out);
}

// round 16
// speedup vs baseline: 1.0052x; 1.0052x over previous
#include <cuda_runtime.h>
#include <cuda_fp16.h>
#include <cstdint>

// ---------------- problem constants ----------------
#define B_     4
#define C_     512
#define TH_    16384
#define MTOT_  (B_ * TH_)
#define KW_    768
#define AUX_   256
#define OUT_   512

// ---------------- tiling ----------------
#define BM 64
#define BK 32
#define NS (C_ / BK)            // 16 stages
#define NTHR 512
// stage layout (bytes): A 4K | W 40960
#define ST_A    0
#define ST_W    4096
#define ST_SZ   45056
#define WROWB 80

// epilogue smem (floats, overlaid on stage memory)
#define EZS 520
#define ZB_F   (BM * EZS)               // 33280
#define PART_F (ZB_F)                   // part[8][64][2]
#define MU_F   (PART_F + 1024)
#define RS_F   (MU_F + 64)
#define SMEM_TOTAL 137728

// ---------------- device scratch ----------------
__device__ __align__(16) __half g_Wh[(size_t)OUT_ * C_];
__device__ float g_sproj[B_ * OUT_];

// ---------------- asm helpers ----------------
__device__ __forceinline__ uint32_t smem_u32(const void* p) {
    uint32_t a;
    asm("{ .reg .u64 t; cvta.to.shared.u64 t, %1; cvt.u32.u64 %0, t; }" : "=r"(a) : "l"(p));
    return a;
}
__device__ __forceinline__ void cp_async16(uint32_t dst, const void* src) {
    asm volatile("cp.async.cg.shared.global [%0], [%1], 16;" :: "r"(dst), "l"(src) : "memory");
}
#define CP_COMMIT() asm volatile("cp.async.commit_group;" ::: "memory")
#define CP_WAIT(n)  asm volatile("cp.async.wait_group %0;" :: "n"(n) : "memory")

__device__ __forceinline__ void ldm_x4(uint32_t* r, uint32_t addr) {
    asm volatile("ldmatrix.sync.aligned.m8n8.x4.shared.b16 {%0,%1,%2,%3}, [%4];"
                 : "=r"(r[0]), "=r"(r[1]), "=r"(r[2]), "=r"(r[3]) : "r"(addr));
}
__device__ __forceinline__ void ldm_x4_t(uint32_t* r, uint32_t addr) {
    asm volatile("ldmatrix.sync.aligned.m8n8.x4.trans.shared.b16 {%0,%1,%2,%3}, [%4];"
                 : "=r"(r[0]), "=r"(r[1]), "=r"(r[2]), "=r"(r[3]) : "r"(addr));
}
__device__ __forceinline__ void mma16816(float* d, const uint32_t* a, const uint32_t* b) {
    asm volatile(
        "mma.sync.aligned.m16n8k16.row.col.f32.f16.f16.f32 "
        "{%0,%1,%2,%3},{%4,%5,%6,%7},{%8,%9},{%0,%1,%2,%3};"
        : "+f"(d[0]), "+f"(d[1]), "+f"(d[2]), "+f"(d[3])
        : "r"(a[0]), "r"(a[1]), "r"(a[2]), "r"(a[3]), "r"(b[0]), "r"(b[1]));
}
__device__ __forceinline__ void sts64(uint32_t dst, uint32_t a, uint32_t b) {
    asm volatile("st.shared.v2.b32 [%0], {%1,%2};" :: "r"(dst), "r"(a), "r"(b) : "memory");
}

// convert 4 floats -> fp16 pair-packed (2 u32)
__device__ __forceinline__ void cvt4h(const float* f, uint32_t* hi) {
    unsigned short h[4];
#pragma unroll
    for (int j = 0; j < 4; ++j) h[j] = __half_as_ushort(__float2half_rn(f[j]));
    hi[0] = (uint32_t)h[0] | ((uint32_t)h[1] << 16);
    hi[1] = (uint32_t)h[2] | ((uint32_t)h[3] << 16);
}

// ---------------- prep kernels ----------------
__global__ void sproj_kernel(const float* __restrict__ s, const float* __restrict__ W,
                             const float* __restrict__ bias) {
    __shared__ float ss[AUX_];
    const int b = blockIdx.x, o0 = blockIdx.y * 64;
    const int tid = threadIdx.x, lane = tid & 31, warp = tid >> 5;
    if (tid < AUX_) ss[tid] = s[b * AUX_ + tid];
    __syncthreads();
    float sl[8];
    *(float4*)&sl[0] = *(const float4*)&ss[lane * 8];
    *(float4*)&sl[4] = *(const float4*)&ss[lane * 8 + 4];
#pragma unroll
    for (int i = 0; i < 8; ++i) {
        const int o = o0 + warp * 8 + i;
        const float* wr = W + (size_t)o * KW_ + C_ + lane * 8;
        float4 w0 = *(const float4*)wr;
        float4 w1 = *(const float4*)(wr + 4);
        float acc = sl[0] * w0.x + sl[1] * w0.y + sl[2] * w0.z + sl[3] * w0.w +
                    sl[4] * w1.x + sl[5] * w1.y + sl[6] * w1.z + sl[7] * w1.w;
#pragma unroll
        for (int off = 16; off; off >>= 1) acc += __shfl_xor_sync(0xffffffffu, acc, off);
        if (lane == 0) g_sproj[b * OUT_ + o] = acc + bias[o];
    }
}

__global__ void wprep_kernel(const float* __restrict__ W) {
    int n = blockIdx.x, t = threadIdx.x;
#pragma unroll
    for (int r = 0; r < 2; ++r) {
        int k = t + r * 256;
        g_Wh[(size_t)n * C_ + k] = __float2half_rn(W[(size_t)n * KW_ + k]);
    }
}

// ---------------- fused GEMM + PReLU + LN + residual ----------------
__global__ __launch_bounds__(NTHR, 1)
void fused_kernel(const float* __restrict__ x, const float* __restrict__ prelu2_a,
                  const float* __restrict__ lnw, const float* __restrict__ lnb,
                  float* __restrict__ out) {
    extern __shared__ char smem[];
    const uint32_t sb = smem_u32(smem);
    float* smf = (float*)smem;

    const int tid = threadIdx.x, lane = tid & 31, wid = tid >> 5;
    const int wm = wid & 1, wn = wid >> 1;        // 2 x 8 warp grid
    const int mwarp = wm * 32, nwarp = wn * 64;
    const int m0 = blockIdx.x * BM;
    const int bi = m0 >> 14, mb = m0 & (TH_ - 1);
    const float* xb = x + (size_t)bi * C_ * TH_ + mb;

    const int ka = tid >> 4, mo4 = tid & 15;
    const uint32_t a_sts_off = ka * 128 + (((mo4 >> 1) ^ (ka & 7)) << 4) + (mo4 & 1) * 8;
    const float* a_src = xb + (size_t)ka * TH_ + mo4 * 4;

    const int krl = (lane & 7) + ((lane >> 4) & 1) * 8;
    const int mcl = ((lane >> 3) & 1) * 8;
    uint32_t cA[2];
#pragma unroll
    for (int i = 0; i < 2; ++i)
        cA[i] = krl * 128 + ((((mwarp + i * 16 + mcl) >> 3) ^ (krl & 7)) << 4);
    const int nll = (lane & 7) + ((lane >> 4) & 1) * 8;
    const int kcl = ((lane >> 3) & 1) * 8;
    const uint32_t cB = (nwarp + nll) * WROWB + kcl * 2;

    float acc[2][8][4];
#pragma unroll
    for (int i = 0; i < 2; ++i)
#pragma unroll
        for (int j = 0; j < 8; ++j)
#pragma unroll
            for (int q = 0; q < 4; ++q) acc[i][j][q] = 0.f;

    auto issue_W = [&](int s) {
        const uint32_t wb = sb + (s & 1) * ST_SZ + ST_W;
        const int kk = s * BK;
#pragma unroll
        for (int r = 0; r < 4; ++r) {
            const int n = r * 128 + (tid >> 2);
            const int kc = tid & 3;
            cp_async16(wb + n * WROWB + kc * 16, g_Wh + (size_t)n * C_ + kk + kc * 8);
        }
        CP_COMMIT();
    };
    auto ldg_A = [&](int s, float4& f) {
        f = *(const float4*)(a_src + (size_t)s * BK * TH_);
    };
    auto sts_A = [&](int s, const float4& f) {
        const uint32_t ab = sb + (s & 1) * ST_SZ;
        uint32_t hi[2];
        cvt4h((const float*)&f, hi);
        sts64(ab + ST_A + a_sts_off, hi[0], hi[1]);
    };

    // ---- prologue ----
    {
        float4 f0;
        ldg_A(0, f0);
        issue_W(0);
        sts_A(0, f0);
        CP_WAIT(0);
        __syncthreads();
    }

    // ---- mainloop ----
    for (int s = 0; s < NS; ++s) {
        const bool pf = (s + 1 < NS);
        float4 fr;
        if (pf) { issue_W(s + 1); ldg_A(s + 1, fr); }

        const uint32_t stb = sb + (s & 1) * ST_SZ;
#pragma unroll
        for (int h16 = 0; h16 < 2; ++h16) {
            uint32_t aH[2][4];
#pragma unroll
            for (int i = 0; i < 2; ++i)
                ldm_x4_t(aH[i], stb + ST_A + h16 * 2048 + cA[i]);
#pragma unroll
            for (int j2 = 0; j2 < 4; ++j2) {
                uint32_t bH[4];
                ldm_x4(bH, stb + ST_W + cB + j2 * (16 * WROWB) + h16 * 32);
#pragma unroll
                for (int i = 0; i < 2; ++i)
#pragma unroll
                    for (int jj = 0; jj < 2; ++jj)
                        mma16816(acc[i][j2 * 2 + jj], aH[i], &bH[jj * 2]);
            }
        }
        if (pf) {
            sts_A(s + 1, fr);
            CP_WAIT(0);
        }
        __syncthreads();
    }

    // ---- in-kernel epilogue ----
    const float a2 = *prelu2_a;
    float2 spv[8];
#pragma unroll
    for (int j = 0; j < 8; ++j)
        spv[j] = *(const float2*)&g_sproj[bi * OUT_ + nwarp + j * 8 + (lane & 3) * 2];

    float su[4] = {0.f, 0.f, 0.f, 0.f}, sq[4] = {0.f, 0.f, 0.f, 0.f};
#pragma unroll
    for (int i = 0; i < 2; ++i)
#pragma unroll
        for (int j = 0; j < 8; ++j)
#pragma unroll
            for (int q = 0; q < 4; ++q) {
                float v = acc[i][j][q] + ((q & 1) ? spv[j].y : spv[j].x);
                v = (v >= 0.f) ? v : a2 * v;
                acc[i][j][q] = v;
                const int si = i * 2 + (q >> 1);
                su[si] += v; sq[si] += v * v;
            }
#pragma unroll
    for (int si = 0; si < 4; ++si) {
#pragma unroll
        for (int off = 1; off <= 2; off <<= 1) {
            su[si] += __shfl_xor_sync(0xffffffffu, su[si], off);
            sq[si] += __shfl_xor_sync(0xffffffffu, sq[si], off);
        }
    }
    if ((lane & 3) == 0) {
#pragma unroll
        for (int si = 0; si < 4; ++si) {
            const int tok = mwarp + (si >> 1) * 16 + (si & 1) * 8 + (lane >> 2);
            smf[PART_F + wn * 128 + tok * 2] = su[si];
            smf[PART_F + wn * 128 + tok * 2 + 1] = sq[si];
        }
    }
#pragma unroll
    for (int i = 0; i < 2; ++i) {
        const int tok = mwarp + i * 16 + (lane >> 2);
#pragma unroll
        for (int j = 0; j < 8; ++j) {
            const int c = nwarp + j * 8 + (lane & 3) * 2;
            *(float2*)&smf[tok * EZS + c] = make_float2(acc[i][j][0], acc[i][j][1]);
            *(float2*)&smf[(tok + 8) * EZS + c] = make_float2(acc[i][j][2], acc[i][j][3]);
        }
    }
    __syncthreads();

    if (tid < 64) {
        float s0 = 0.f, s1 = 0.f;
#pragma unroll
        for (int w = 0; w < 8; ++w) {
            s0 += smf[PART_F + w * 128 + tid * 2];
            s1 += smf[PART_F + w * 128 + tid * 2 + 1];
        }
        const float mu = s0 * (1.f / 512.f);
        smf[MU_F + tid] = mu;
        smf[RS_F + tid] = rsqrtf(s1 * (1.f / 512.f) - mu * mu + 1e-8f);
    }
    __syncthreads();

    {
        const int o = tid;
        const float lw = lnw[o], lb = lnb[o];
        const size_t gbase = ((size_t)(bi * OUT_ + o)) * TH_ + mb;
#pragma unroll 4
        for (int mq = 0; mq < BM; mq += 4) {
            float4 xv = *(const float4*)(x + gbase + mq);
            float4 yv;
            yv.x = xv.x + (smf[(mq + 0) * EZS + o] - smf[MU_F + mq + 0]) * smf[RS_F + mq + 0] * lw + lb;
            yv.y = xv.y + (smf[(mq + 1) * EZS + o] - smf[MU_F + mq + 1]) * smf[RS_F + mq + 1] * lw + lb;
            yv.z = xv.z + (smf[(mq + 2) * EZS + o] - smf[MU_F + mq + 2]) * smf[RS_F + mq + 2] * lw + lb;
            yv.w = xv.w + (smf[(mq + 3) * EZS + o] - smf[MU_F + mq + 3]) * smf[RS_F + mq + 3] * lw + lb;
            *(float4*)(out + gbase + mq) = yv;
        }
    }
}

// ---------------- launch ----------------
extern "C" void kernel_launch(void* const* d_in, const int* in_sizes, int n_in,
                              void* d_out, int out_size) {
    (void)in_sizes; (void)n_in; (void)out_size;
    const float* x        = (const float*)d_in[0];
    const float* s        = (const float*)d_in[1];
    const float* W        = (const float*)d_in[5];
    const float* bias     = (const float*)d_in[6];
    const float* prelu2_a = (const float*)d_in[7];
    const float* ln2_w    = (const float*)d_in[8];
    const float* ln2_b    = (const float*)d_in[9];
    float* out = (float*)d_out;

    cudaFuncSetAttribute(fused_kernel, cudaFuncAttributeMaxDynamicSharedMemorySize, SMEM_TOTAL);

    sproj_kernel<<<dim3(B_, OUT_ / 64), 256>>>(s, W, bias);
    wprep_kernel<<<OUT_, 256>>>(W);
    fused_kernel<<<MTOT_ / BM, NTHR, SMEM_TOTAL>>>(x, prelu2_a, ln2_w, ln2_b, out);
}